// round 5
// baseline (speedup 1.0000x reference)
#include <cuda_runtime.h>

// Problem constants
#define NB   4
#define SEQ  4096
#define ED   1024
#define VOC  32000
#define QKV3 3072

// token index loader: x is int32 (JAX downcasts int64 without x64 mode); clamp defensively
__device__ __forceinline__ size_t tok(const int* __restrict__ x, size_t i) {
    unsigned v = (unsigned)x[i];
    return (size_t)(v < VOC ? v : VOC - 1);
}

// ---------------- scratch (device globals; no allocation allowed) ----------------
__device__ float g_qpart[NB][8][ED];     // partial q = h_last @ Wq  (e-chunked)
__device__ float g_qt[NB][ED];           // q~ = Wk @ q
__device__ float g_qbk[NB];              // q . b_k
__device__ float g_w[NB][SEQ];           // logits -> softmax weights
__device__ float g_part[NB][64][ED];     // partial hbar (j-chunked)
__device__ float g_hbar[NB][ED];         // attention-weighted embed sum
__device__ float g_hfpart[NB][8][ED];    // partial hbar @ Wv (e-chunked)
__device__ float g_hf[NB][ED];           // final hidden = attnout + h_last
__device__ float g_opart[4][NB][VOC];    // partial output logits (e-chunked)

// ---------------- K1: partial q[d] = sum_e h_last[e] * Wq[e,d] over e-chunk ----------------
__global__ void k1_qpart(const int* __restrict__ x,
                         const float* __restrict__ embed,
                         const float* __restrict__ qkv_w) {
    int b = blockIdx.y, c = blockIdx.x;          // c: e-chunk of 128
    __shared__ float sh[128];
    size_t idx = tok(x, (size_t)b * SEQ + SEQ - 1);
    const float* row = embed + idx * ED + c * 128;
    if (threadIdx.x < 128) sh[threadIdx.x] = row[threadIdx.x];
    __syncthreads();
    for (int d = threadIdx.x; d < ED; d += 256) {
        float acc = 0.f;
        const float* w = qkv_w + (size_t)(c * 128) * QKV3 + d;   // Wq columns
        #pragma unroll 8
        for (int e = 0; e < 128; e++) acc = fmaf(sh[e], w[(size_t)e * QKV3], acc);
        g_qpart[b][c][d] = acc;
    }
}

// ---------------- K1b: q~ = Wk @ q (row-contiguous dots), plus q.b_k ----------------
__global__ void k1b_qt(const float* __restrict__ qkv_w,
                       const float* __restrict__ qkv_b) {
    int b = blockIdx.y;
    __shared__ float sq[ED];
    for (int i = threadIdx.x; i < ED; i += 256) {
        float a = qkv_b[i];                       // Wq bias folds in here
        #pragma unroll
        for (int c = 0; c < 8; c++) a += g_qpart[b][c][i];
        sq[i] = a;
    }
    __syncthreads();
    int warp = threadIdx.x >> 5, lane = threadIdx.x & 31;
    int nw = gridDim.x * 8;
    const float4* q4 = (const float4*)sq;
    for (int e = blockIdx.x * 8 + warp; e < ED; e += nw) {
        const float4* w4 = (const float4*)(qkv_w + (size_t)e * QKV3 + ED);  // Wk row e
        float acc = 0.f;
        #pragma unroll 4
        for (int i = lane; i < 256; i += 32) {
            float4 w = w4[i], q = q4[i];
            acc += w.x * q.x + w.y * q.y + w.z * q.z + w.w * q.w;
        }
        #pragma unroll
        for (int o = 16; o; o >>= 1) acc += __shfl_down_sync(0xffffffffu, acc, o);
        if (!lane) g_qt[b][e] = acc;
    }
    if (blockIdx.x == 0) {                        // q . b_k
        __shared__ float red[256];
        float p = 0.f;
        for (int d = threadIdx.x; d < ED; d += 256) p += sq[d] * qkv_b[ED + d];
        red[threadIdx.x] = p; __syncthreads();
        for (int s = 128; s; s >>= 1) {
            if (threadIdx.x < s) red[threadIdx.x] += red[threadIdx.x + s];
            __syncthreads();
        }
        if (threadIdx.x == 0) g_qbk[b] = red[0];
    }
}

// ---------------- K2: logits[b][j] = (q~ . embed[x[b,j]] + q.bk) / 32 ----------------
__global__ void k2_logits(const int* __restrict__ x,
                          const float* __restrict__ embed) {
    int b = blockIdx.y;
    __shared__ float4 sq[256];
    for (int i = threadIdx.x; i < 256; i += 256) sq[i] = ((const float4*)g_qt[b])[i];
    __syncthreads();
    int warp = threadIdx.x >> 5, lane = threadIdx.x & 31;
    int j = blockIdx.x * 8 + warp;
    const float4* r4 = (const float4*)(embed + tok(x, (size_t)b * SEQ + j) * ED);
    float acc = 0.f;
    #pragma unroll 4
    for (int i = lane; i < 256; i += 32) {
        float4 r = r4[i], q = sq[i];
        acc += r.x * q.x + r.y * q.y + r.z * q.z + r.w * q.w;
    }
    #pragma unroll
    for (int o = 16; o; o >>= 1) acc += __shfl_down_sync(0xffffffffu, acc, o);
    if (!lane) g_w[b][j] = (acc + g_qbk[b]) * 0.03125f;   // 1/sqrt(1024)=1/32
}

// ---------------- K3: softmax over 4096 logits per batch ----------------
__global__ void k3_softmax() {
    int b = blockIdx.x, tid = threadIdx.x;
    __shared__ float red[1024];
    float m = -1e30f;
    for (int j = tid; j < SEQ; j += 1024) m = fmaxf(m, g_w[b][j]);
    red[tid] = m; __syncthreads();
    for (int s = 512; s; s >>= 1) {
        if (tid < s) red[tid] = fmaxf(red[tid], red[tid + s]);
        __syncthreads();
    }
    float M = red[0]; __syncthreads();
    float sum = 0.f;
    for (int j = tid; j < SEQ; j += 1024) {
        float e = expf(g_w[b][j] - M);
        g_w[b][j] = e;
        sum += e;
    }
    red[tid] = sum; __syncthreads();
    for (int s = 512; s; s >>= 1) {
        if (tid < s) red[tid] += red[tid + s];
        __syncthreads();
    }
    float inv = 1.0f / red[0];
    for (int j = tid; j < SEQ; j += 1024) g_w[b][j] *= inv;
}

// ---------------- K4: partial hbar[e] = sum_{j in chunk} w_j * embed[x[b,j]][e] ----------------
__global__ void k4_part(const int* __restrict__ x,
                        const float* __restrict__ embed) {
    int b = blockIdx.y, c = blockIdx.x, e = threadIdx.x;
    const int* xb = x + (size_t)b * SEQ + c * 64;
    const float* wb = g_w[b] + c * 64;
    float acc = 0.f;
    #pragma unroll 4
    for (int jj = 0; jj < 64; jj++) {
        unsigned v = (unsigned)xb[jj];
        size_t idx = (size_t)(v < VOC ? v : VOC - 1);
        acc = fmaf(wb[jj], embed[idx * ED + e], acc);
    }
    g_part[b][c][e] = acc;
}

__global__ void k4b_red() {
    int b = blockIdx.x, e = threadIdx.x;
    float a = 0.f;
    #pragma unroll
    for (int c = 0; c < 64; c++) a += g_part[b][c][e];
    g_hbar[b][e] = a;
}

// ---------------- K5: partial (hbar @ Wv)[d] over e-chunk ----------------
__global__ void k5_part(const float* __restrict__ qkv_w) {
    int b = blockIdx.y, c = blockIdx.x;
    __shared__ float sh[128];
    if (threadIdx.x < 128) sh[threadIdx.x] = g_hbar[b][c * 128 + threadIdx.x];
    __syncthreads();
    for (int d = threadIdx.x; d < ED; d += 256) {
        float acc = 0.f;
        const float* w = qkv_w + (size_t)(c * 128) * QKV3 + 2048 + d;  // Wv columns
        #pragma unroll 8
        for (int e = 0; e < 128; e++) acc = fmaf(sh[e], w[(size_t)e * QKV3], acc);
        g_hfpart[b][c][d] = acc;
    }
}

__global__ void k5b_red(const int* __restrict__ x,
                        const float* __restrict__ embed,
                        const float* __restrict__ qkv_b) {
    int b = blockIdx.x, d = threadIdx.x;
    float a = qkv_b[2048 + d];                    // b_v
    #pragma unroll
    for (int c = 0; c < 8; c++) a += g_hfpart[b][c][d];
    size_t idx = tok(x, (size_t)b * SEQ + SEQ - 1);
    g_hf[b][d] = a + embed[idx * ED + d];         // residual with h_last
}

// ---------------- K6: partial out[b][v] = sum_{e in chunk} hf[b][e]*out_w[e][v] ----------------
__global__ void k6_part(const float* __restrict__ out_w) {
    int vt = blockIdx.x * 512 + threadIdx.x * 4;
    int ec = blockIdx.y * 256;
    __shared__ float sh[NB][256];
    for (int i = threadIdx.x; i < 1024; i += 128)
        sh[i >> 8][i & 255] = g_hf[i >> 8][ec + (i & 255)];
    __syncthreads();
    if (vt >= VOC) return;
    float4 a0 = {0,0,0,0}, a1 = a0, a2 = a0, a3 = a0;
    const float* base = out_w + (size_t)ec * VOC + vt;
    #pragma unroll 4
    for (int e = 0; e < 256; e++) {
        float4 w = *(const float4*)(base + (size_t)e * VOC);
        float h0 = sh[0][e], h1 = sh[1][e], h2 = sh[2][e], h3 = sh[3][e];
        a0.x = fmaf(h0, w.x, a0.x); a0.y = fmaf(h0, w.y, a0.y);
        a0.z = fmaf(h0, w.z, a0.z); a0.w = fmaf(h0, w.w, a0.w);
        a1.x = fmaf(h1, w.x, a1.x); a1.y = fmaf(h1, w.y, a1.y);
        a1.z = fmaf(h1, w.z, a1.z); a1.w = fmaf(h1, w.w, a1.w);
        a2.x = fmaf(h2, w.x, a2.x); a2.y = fmaf(h2, w.y, a2.y);
        a2.z = fmaf(h2, w.z, a2.z); a2.w = fmaf(h2, w.w, a2.w);
        a3.x = fmaf(h3, w.x, a3.x); a3.y = fmaf(h3, w.y, a3.y);
        a3.z = fmaf(h3, w.z, a3.z); a3.w = fmaf(h3, w.w, a3.w);
    }
    int ecb = blockIdx.y;
    *(float4*)(&g_opart[ecb][0][vt]) = a0;
    *(float4*)(&g_opart[ecb][1][vt]) = a1;
    *(float4*)(&g_opart[ecb][2][vt]) = a2;
    *(float4*)(&g_opart[ecb][3][vt]) = a3;
}

__global__ void k6b_red(const float* __restrict__ out_b,
                        float* __restrict__ out) {
    int b = blockIdx.y;
    int v = blockIdx.x * 256 + threadIdx.x;       // 125*256 = 32000 exactly
    float a = out_b[v];
    a += g_opart[0][b][v] + g_opart[1][b][v] + g_opart[2][b][v] + g_opart[3][b][v];
    out[(size_t)b * VOC + v] = a;
}

// ---------------- launch ----------------
extern "C" void kernel_launch(void* const* d_in, const int* in_sizes, int n_in,
                              void* d_out, int out_size) {
    const int* x           = (const int*)d_in[0];
    const float* embed     = (const float*)d_in[1];
    const float* qkv_w     = (const float*)d_in[2];
    const float* qkv_b     = (const float*)d_in[3];
    const float* out_w     = (const float*)d_in[4];
    const float* out_b     = (const float*)d_in[5];
    float* out             = (float*)d_out;

    k1_qpart <<<dim3(8, NB),  256>>>(x, embed, qkv_w);
    k1b_qt   <<<dim3(32, NB), 256>>>(qkv_w, qkv_b);
    k2_logits<<<dim3(512, NB),256>>>(x, embed);
    k3_softmax<<<NB, 1024>>>();
    k4_part  <<<dim3(64, NB), 1024>>>(x, embed);
    k4b_red  <<<NB, 1024>>>();
    k5_part  <<<dim3(8, NB),  256>>>(qkv_w);
    k5b_red  <<<NB, 1024>>>(x, embed, qkv_b);
    k6_part  <<<dim3(63, 4),  128>>>(out_w);
    k6b_red  <<<dim3(125, NB),256>>>(out_b, out);
}

// round 6
// speedup vs baseline: 2.0327x; 2.0327x over previous
#include <cuda_runtime.h>

#define NB   4
#define SEQ  4096
#define ED   1024
#define VOC  32000
#define QKV3 3072

__device__ __forceinline__ size_t tok(const int* __restrict__ x, size_t i) {
    unsigned v = (unsigned)x[i];
    return (size_t)(v < VOC ? v : VOC - 1);
}

// ---------------- scratch ----------------
__device__ float g_qpart[NB][16][ED];    // partial q over e-chunks of 64
__device__ float g_qt[NB][ED];           // q~ = Wk @ q
__device__ float g_part[NB][128][ED];    // partial unnormalized hbar (j-chunks of 32)
__device__ float g_psum[NB][128];        // partial sum of exp weights
__device__ float g_hfpart[NB][16][ED];   // partial hbar @ Wv (e-chunks of 64)
__device__ float g_opart[8][NB][VOC];    // partial output logits (e-chunks of 128)

// ---------------- K1: partial q[d] over 64-e chunk, 256-d chunk ----------------
// grid (64, NB): blockIdx.x = dc*16 + ec
__global__ void k1_qpart(const int* __restrict__ x,
                         const float* __restrict__ embed,
                         const float* __restrict__ qkv_w) {
    int b = blockIdx.y;
    int ec = blockIdx.x & 15, dc = blockIdx.x >> 4;
    __shared__ float sh[64];
    size_t idx = tok(x, (size_t)b * SEQ + SEQ - 1);
    if (threadIdx.x < 64) sh[threadIdx.x] = embed[idx * ED + ec * 64 + threadIdx.x];
    __syncthreads();
    int d = dc * 256 + threadIdx.x;
    float acc = 0.f;
    const float* w = qkv_w + (size_t)(ec * 64) * QKV3 + d;   // Wq
    #pragma unroll 16
    for (int e = 0; e < 64; e++) acc = fmaf(sh[e], w[(size_t)e * QKV3], acc);
    g_qpart[b][ec][d] = acc;
}

// ---------------- K1b: q~ = Wk @ (q + bq) ----------------
// grid (32, NB), 256 threads
__global__ void k1b_qt(const float* __restrict__ qkv_w,
                       const float* __restrict__ qkv_b) {
    int b = blockIdx.y;
    __shared__ float sq[ED];
    for (int i = threadIdx.x; i < ED; i += 256) {
        float a = qkv_b[i];
        #pragma unroll
        for (int c = 0; c < 16; c++) a += g_qpart[b][c][i];
        sq[i] = a;
    }
    __syncthreads();
    int warp = threadIdx.x >> 5, lane = threadIdx.x & 31;
    const float4* q4 = (const float4*)sq;
    for (int e = blockIdx.x * 8 + warp; e < ED; e += 256) {
        const float4* w4 = (const float4*)(qkv_w + (size_t)e * QKV3 + ED);  // Wk row e
        float acc = 0.f;
        #pragma unroll 4
        for (int i = lane; i < 256; i += 32) {
            float4 w = w4[i], q = q4[i];
            acc += w.x * q.x + w.y * q.y + w.z * q.z + w.w * q.w;
        }
        #pragma unroll
        for (int o = 16; o; o >>= 1) acc += __shfl_xor_sync(0xffffffffu, acc, o);
        if (!lane) g_qt[b][e] = acc;
    }
}

// ---------------- JFUSE: logits + exp + weighted-embed accumulate, one gather pass ----------------
// grid (128, NB), 256 threads (8 warps), 32 j per block, 4 j per warp
__global__ void jfuse(const int* __restrict__ x,
                      const float* __restrict__ embed) {
    int b = blockIdx.y, chunk = blockIdx.x;
    int warp = threadIdx.x >> 5, lane = threadIdx.x & 31;
    __shared__ float4 sq4[256];        // q~
    __shared__ float sred[8][ED];      // 32KB per-warp partials
    __shared__ float spsum[8];
    for (int i = threadIdx.x; i < 256; i += 256) sq4[i] = ((const float4*)g_qt[b])[i];
    __syncthreads();

    float4 acc[8];
    #pragma unroll
    for (int i = 0; i < 8; i++) acc[i] = make_float4(0.f, 0.f, 0.f, 0.f);
    float wsum = 0.f;

    #pragma unroll
    for (int jj = 0; jj < 4; jj++) {
        int j = chunk * 32 + warp * 4 + jj;
        const float4* r4 = (const float4*)(embed + tok(x, (size_t)b * SEQ + j) * ED);
        float4 row[8];
        float dot = 0.f;
        #pragma unroll
        for (int i = 0; i < 8; i++) {
            row[i] = r4[lane + 32 * i];
            float4 q = sq4[lane + 32 * i];
            dot += row[i].x * q.x + row[i].y * q.y + row[i].z * q.z + row[i].w * q.w;
        }
        #pragma unroll
        for (int o = 16; o; o >>= 1) dot += __shfl_xor_sync(0xffffffffu, dot, o);
        float wj = expf(dot * 0.03125f);      // 1/sqrt(1024); shift-invariant softmax, no max-sub
        wsum += wj;
        #pragma unroll
        for (int i = 0; i < 8; i++) {
            acc[i].x = fmaf(wj, row[i].x, acc[i].x);
            acc[i].y = fmaf(wj, row[i].y, acc[i].y);
            acc[i].z = fmaf(wj, row[i].z, acc[i].z);
            acc[i].w = fmaf(wj, row[i].w, acc[i].w);
        }
    }
    float4* myred = (float4*)sred[warp];
    #pragma unroll
    for (int i = 0; i < 8; i++) myred[lane + 32 * i] = acc[i];
    if (!lane) spsum[warp] = wsum;
    __syncthreads();
    for (int p = threadIdx.x; p < ED; p += 256) {
        float s = 0.f;
        #pragma unroll
        for (int w = 0; w < 8; w++) s += sred[w][p];
        g_part[b][chunk][p] = s;
    }
    if (threadIdx.x == 0) {
        float s = 0.f;
        #pragma unroll
        for (int w = 0; w < 8; w++) s += spsum[w];
        g_psum[b][chunk] = s;
    }
}

// ---------------- K5: reduce hbar (normalize) + partial hbar@Wv over 64-e chunk ----------------
// grid (16, NB), 256 threads
__global__ void k5_part(const float* __restrict__ qkv_w) {
    int b = blockIdx.y, c = blockIdx.x;
    int tid = threadIdx.x;
    __shared__ float dsum[128];
    __shared__ float part[4][64];
    __shared__ float hb[64];
    if (tid < 128) dsum[tid] = g_psum[b][tid];
    // hbar partials: thread (g=tid>>6, el=tid&63) sums 32 j-chunks
    int g = tid >> 6, el = tid & 63;
    float s = 0.f;
    #pragma unroll 8
    for (int jc = g * 32; jc < g * 32 + 32; jc++) s += g_part[b][jc][c * 64 + el];
    part[g][el] = s;
    __syncthreads();
    if (tid < 64) dsum[tid] += dsum[tid + 64];
    __syncthreads();
    if (tid < 32) dsum[tid] += dsum[tid + 32];
    __syncthreads();
    if (tid < 32) {
        float v = dsum[tid];
        #pragma unroll
        for (int o = 16; o; o >>= 1) v += __shfl_xor_sync(0xffffffffu, v, o);
        if (!tid) dsum[0] = v;
    }
    __syncthreads();
    if (tid < 64) {
        hb[tid] = (part[0][tid] + part[1][tid] + part[2][tid] + part[3][tid]) / dsum[0];
    }
    __syncthreads();
    for (int d = tid; d < ED; d += 256) {
        float a = 0.f;
        const float* w = qkv_w + (size_t)(c * 64) * QKV3 + 2048 + d;  // Wv
        #pragma unroll 16
        for (int e = 0; e < 64; e++) a = fmaf(hb[e], w[(size_t)e * QKV3], a);
        g_hfpart[b][c][d] = a;
    }
}

// ---------------- K6: build hf slice (reduce + bv + residual) then big vocab GEMV partial ----------------
// grid (63, 8), 128 threads
__global__ void k6_part(const float* __restrict__ out_w,
                        const float* __restrict__ qkv_b,
                        const int* __restrict__ x,
                        const float* __restrict__ embed) {
    int ecb = blockIdx.y;                 // e-chunk of 128
    int tid = threadIdx.x;
    __shared__ float sh[NB][128];
    int e = ecb * 128 + tid;
    #pragma unroll
    for (int b = 0; b < NB; b++) {
        float a = qkv_b[2048 + e];
        #pragma unroll
        for (int c = 0; c < 16; c++) a += g_hfpart[b][c][e];
        a += embed[tok(x, (size_t)b * SEQ + SEQ - 1) * ED + e];
        sh[b][tid] = a;
    }
    __syncthreads();
    int vt = blockIdx.x * 512 + tid * 4;
    if (vt >= VOC) return;
    float4 a0 = {0,0,0,0}, a1 = a0, a2 = a0, a3 = a0;
    const float* base = out_w + (size_t)(ecb * 128) * VOC + vt;
    #pragma unroll 8
    for (int ee = 0; ee < 128; ee++) {
        float4 w = *(const float4*)(base + (size_t)ee * VOC);
        float h0 = sh[0][ee], h1 = sh[1][ee], h2 = sh[2][ee], h3 = sh[3][ee];
        a0.x = fmaf(h0, w.x, a0.x); a0.y = fmaf(h0, w.y, a0.y);
        a0.z = fmaf(h0, w.z, a0.z); a0.w = fmaf(h0, w.w, a0.w);
        a1.x = fmaf(h1, w.x, a1.x); a1.y = fmaf(h1, w.y, a1.y);
        a1.z = fmaf(h1, w.z, a1.z); a1.w = fmaf(h1, w.w, a1.w);
        a2.x = fmaf(h2, w.x, a2.x); a2.y = fmaf(h2, w.y, a2.y);
        a2.z = fmaf(h2, w.z, a2.z); a2.w = fmaf(h2, w.w, a2.w);
        a3.x = fmaf(h3, w.x, a3.x); a3.y = fmaf(h3, w.y, a3.y);
        a3.z = fmaf(h3, w.z, a3.z); a3.w = fmaf(h3, w.w, a3.w);
    }
    *(float4*)(&g_opart[ecb][0][vt]) = a0;
    *(float4*)(&g_opart[ecb][1][vt]) = a1;
    *(float4*)(&g_opart[ecb][2][vt]) = a2;
    *(float4*)(&g_opart[ecb][3][vt]) = a3;
}

// ---------------- K6b: final reduce ----------------
__global__ void k6b_red(const float* __restrict__ out_b,
                        float* __restrict__ out) {
    int b = blockIdx.y;
    int v = blockIdx.x * 256 + threadIdx.x;       // 125*256 = 32000 exactly
    float a = out_b[v];
    #pragma unroll
    for (int c = 0; c < 8; c++) a += g_opart[c][b][v];
    out[(size_t)b * VOC + v] = a;
}

// ---------------- launch ----------------
extern "C" void kernel_launch(void* const* d_in, const int* in_sizes, int n_in,
                              void* d_out, int out_size) {
    const int* x           = (const int*)d_in[0];
    const float* embed     = (const float*)d_in[1];
    const float* qkv_w     = (const float*)d_in[2];
    const float* qkv_b     = (const float*)d_in[3];
    const float* out_w     = (const float*)d_in[4];
    const float* out_b     = (const float*)d_in[5];
    float* out             = (float*)d_out;

    k1_qpart <<<dim3(64, NB),  256>>>(x, embed, qkv_w);
    k1b_qt   <<<dim3(32, NB),  256>>>(qkv_w, qkv_b);
    jfuse    <<<dim3(128, NB), 256>>>(x, embed);
    k5_part  <<<dim3(16, NB),  256>>>(qkv_w);
    k6_part  <<<dim3(63, 8),   128>>>(out_w, qkv_b, x, embed);
    k6b_red  <<<dim3(125, NB), 256>>>(out_b, out);
}